// round 13
// baseline (speedup 1.0000x reference)
#include <cuda_runtime.h>
#include <math.h>
#include <stdint.h>

// Problem constants
#define SEQ   256
#define BAT   64
#define EMB   300
#define HID2  256          // H2
#define NJ    2048         // 4*H2 * 2 directions
#define NTAG  10
#define NROWS 16384        // SEQ*BAT
#define CL    8            // cluster size

typedef unsigned long long ull;

// ---------------- packed fp32x2 helpers (sm_103a FFMA2) ----------------
__device__ __forceinline__ void fma2(ull &d, ull a, ull b) {
    asm("fma.rn.f32x2 %0, %1, %2, %0;" : "+l"(d) : "l"(a), "l"(b));
}
__device__ __forceinline__ float2 unpack2(ull v) {
    float2 r; asm("mov.b64 {%0,%1}, %2;" : "=f"(r.x), "=f"(r.y) : "l"(v)); return r;
}
__device__ __forceinline__ unsigned smem_u32(const void* p) {
    unsigned a;
    asm("{ .reg .u64 t; cvta.to.shared.u64 t, %1; cvt.u32.u64 %0, t; }" : "=r"(a) : "l"(p));
    return a;
}
__device__ __forceinline__ unsigned mapa_u32(unsigned saddr, int r) {
    unsigned d; asm("mapa.shared::cluster.u32 %0, %1, %2;" : "=r"(d) : "r"(saddr), "r"(r));
    return d;
}
__device__ __forceinline__ void st_remote_f32(unsigned addr, float v) {
    asm volatile("st.shared::cluster.f32 [%0], %1;" :: "r"(addr), "f"(v) : "memory");
}

// ---------------- device scratch (static allocation only) ----------------
__device__ float g_WT[EMB * NJ];                        // wih transposed, [e][j]
__device__ float g_P[(size_t)NROWS * NJ];               // input projections + biases
__device__ float g_Hout[2 * (size_t)NROWS * HID2];      // [dir][s*B+b][k]
__device__ float g_F[NROWS * NTAG + 64];                // feats (B,S,T) flat, padded

// ---------------- kernel 0: transpose wih into [e][j] ----------------
__global__ void transpose_wih(const float* __restrict__ wf, const float* __restrict__ wb) {
    int idx = blockIdx.x * 256 + threadIdx.x;
    if (idx >= EMB * NJ) return;
    int e = idx / NJ, j = idx % NJ;
    g_WT[idx] = (j < 1024) ? wf[j * EMB + e] : wb[(j - 1024) * EMB + e];
}

// ---------------- kernel 1: fused gather + input GEMM (fp32, 64x64 tile) ----
// P[r][j] = sum_e emb[sent[r]][e] * WT[e][j] + bih[j] + bhh[j]
__global__ void __launch_bounds__(256) gemm_input(
    const int* __restrict__ sent, const float* __restrict__ emb,
    const float* __restrict__ bih_f, const float* __restrict__ bhh_f,
    const float* __restrict__ bih_b, const float* __restrict__ bhh_b) {

    __shared__ float As[20][68];   // [k][i], padded stride 68
    __shared__ float Bs[20][64];   // [k][j]
    __shared__ int   toks[64];

    int bx = blockIdx.x & 31;      // N tile (32)
    int by = blockIdx.x >> 5;      // M tile (256)
    int tid = threadIdx.x;
    int row0 = by * 64, col0 = bx * 64;

    if (tid < 64) toks[tid] = sent[row0 + tid];
    __syncthreads();

    int ty = tid >> 4, tx = tid & 15;         // 16x16 thread grid
    int li = tid >> 2;                        // A-load row
    int le = (tid & 3) * 5;                   // A-load e base

    float4 acc[4];
    #pragma unroll
    for (int i = 0; i < 4; i++) acc[i] = make_float4(0.f, 0.f, 0.f, 0.f);

    long tokoff = (long)toks[li] * EMB;

    for (int kc = 0; kc < 15; kc++) {
        int e0 = kc * 20;
        const float* ebase = emb + tokoff + e0 + le;
        #pragma unroll
        for (int q = 0; q < 5; q++) As[le + q][li] = ebase[q];
        #pragma unroll
        for (int u = 0; u < 5; u++) {
            int idx = tid + u * 256;
            int kk = idx >> 6, j = idx & 63;
            Bs[kk][j] = g_WT[(size_t)(e0 + kk) * NJ + col0 + j];
        }
        __syncthreads();
        #pragma unroll
        for (int kk = 0; kk < 20; kk++) {
            float4 b4 = *(const float4*)&Bs[kk][tx * 4];
            float4 a4 = *(const float4*)&As[kk][ty * 4];
            acc[0].x += a4.x * b4.x; acc[0].y += a4.x * b4.y; acc[0].z += a4.x * b4.z; acc[0].w += a4.x * b4.w;
            acc[1].x += a4.y * b4.x; acc[1].y += a4.y * b4.y; acc[1].z += a4.y * b4.z; acc[1].w += a4.y * b4.w;
            acc[2].x += a4.z * b4.x; acc[2].y += a4.z * b4.y; acc[2].z += a4.z * b4.z; acc[2].w += a4.z * b4.w;
            acc[3].x += a4.w * b4.x; acc[3].y += a4.w * b4.y; acc[3].z += a4.w * b4.z; acc[3].w += a4.w * b4.w;
        }
        __syncthreads();
    }

    int jg = col0 + tx * 4;
    float bias[4];
    #pragma unroll
    for (int jj = 0; jj < 4; jj++) {
        int j = jg + jj;
        bias[jj] = (j < 1024) ? (bih_f[j] + bhh_f[j]) : (bih_b[j - 1024] + bhh_b[j - 1024]);
    }
    #pragma unroll
    for (int ii = 0; ii < 4; ii++) {
        float4 v = acc[ii];
        v.x += bias[0]; v.y += bias[1]; v.z += bias[2]; v.w += bias[3];
        *(float4*)&g_P[(size_t)(row0 + ty * 4 + ii) * NJ + jg] = v;
    }
}

// ---------------- kernel 2: clustered bidirectional LSTM recurrence --------
// 16 clusters x 8 CTAs. Cluster = (dir, 8 batches); CTA rank owns 32 hidden
// units (128 Whh rows resident in SMEM). warp = batch, lane = unit:
// each lane computes all 4 gates for (b, u) -> cell state lives in a register.
// Per step: dot products on local h buffer, cell update, DSMEM all-gather of
// h into every cluster CTA's next buffer, split cluster barrier (P prefetch
// hidden between arrive and wait). No L2 flags, no global h traffic.
__global__ void __launch_bounds__(256, 1) __cluster_dims__(CL, 1, 1)
lstm_cluster(const float* __restrict__ whh_f, const float* __restrict__ whh_b,
             const float* __restrict__ h0, const float* __restrict__ c0) {

    extern __shared__ float sm[];
    float* w_s = sm;                 // 128 rows * stride 260 = 33280 floats
    float* h_s = sm + 128 * 260;     // 2 buffers * 8 batches * 256 = 4096 floats
    // total 37376 floats = 149504 B

    int tid  = threadIdx.x;
    int rank = blockIdx.x & 7;       // CTA rank within cluster
    int cid  = blockIdx.x >> 3;      // cluster id (16)
    int dir  = cid >> 3;
    int b0   = (cid & 7) * 8;        // batch base
    const float* whh = dir ? whh_b : whh_f;

    // Load Whh slice: local row rho = g*32 + u' -> global row g*256 + rank*32 + u'
    for (int idx = tid; idx < 128 * 64; idx += 256) {
        int rho = idx >> 6, kq = idx & 63;
        int grow = (rho >> 5) * 256 + rank * 32 + (rho & 31);
        float4 v = *(const float4*)&whh[(size_t)grow * 256 + kq * 4];
        *(float4*)&w_s[rho * 260 + kq * 4] = v;
    }
    // Load h0 (all 256 k for our 8 batches) into buffer 0
    for (int idx = tid; idx < 8 * 64; idx += 256) {
        int bl = idx >> 6, kq = idx & 63;
        float4 v = *(const float4*)&h0[(size_t)(dir * 64 + b0 + bl) * 256 + kq * 4];
        *(float4*)&h_s[bl * 256 + kq * 4] = v;
    }
    __syncthreads();

    const int b = tid >> 5;          // warp = batch (0..7)
    const int l = tid & 31;          // lane = unit within slice
    const int u = rank * 32 + l;     // global hidden unit

    float creg = c0[(size_t)(dir * 64 + b0 + b) * 256 + u];

    // W row pointers (ulonglong2: row stride 260 floats = 65 units)
    const ulonglong2* w0 = (const ulonglong2*)w_s + (0 * 32 + l) * 65;
    const ulonglong2* w1 = (const ulonglong2*)w_s + (1 * 32 + l) * 65;
    const ulonglong2* w2 = (const ulonglong2*)w_s + (2 * 32 + l) * 65;
    const ulonglong2* w3 = (const ulonglong2*)w_s + (3 * 32 + l) * 65;

    // Remote write addresses for h(b,u) in both buffers, all 8 cluster CTAs
    unsigned sA = smem_u32(h_s) + (unsigned)(b * 256 + u) * 4u;
    unsigned sB = sA + 2048u * 4u;
    unsigned remA[8], remB[8];
    #pragma unroll
    for (int r = 0; r < 8; r++) { remA[r] = mapa_u32(sA, r); remB[r] = mapa_u32(sB, r); }

    // P pointer: g_P[(sidx*64 + b0+b)*NJ + dir*1024 + u + g*256], sidx walks +-1
    const float* pptr = g_P + (size_t)((dir ? 255 : 0) * 64 + b0 + b) * NJ + dir * 1024 + u;
    const long pdelta = dir ? -(long)(64 * NJ) : (long)(64 * NJ);
    float Pg0 = pptr[0], Pg1 = pptr[256], Pg2 = pptr[512], Pg3 = pptr[768];
    pptr += pdelta;

    // Hout pointer: g_Hout[dir][(sidx*64 + b0+b)*256 + u]
    float* hout = g_Hout + (size_t)dir * ((size_t)NROWS * HID2)
                + (size_t)(((dir ? 255 : 0) * 64) + b0 + b) * 256 + u;
    const long hdelta = dir ? -(long)(64 * 256) : (long)(64 * 256);

    for (int step = 0; step < 256; step++) {
        int par = step & 1;
        const ulonglong2* h2 = (const ulonglong2*)(h_s + par * 2048 + b * 256);

        ull a0 = 0, a1 = 0, a2 = 0, a3 = 0;
        #pragma unroll 8
        for (int c = 0; c < 64; c++) {
            ulonglong2 hv = h2[c];             // warp-broadcast LDS.128
            ulonglong2 wv;
            wv = w0[c]; fma2(a0, wv.x, hv.x); fma2(a0, wv.y, hv.y);
            wv = w1[c]; fma2(a1, wv.x, hv.x); fma2(a1, wv.y, hv.y);
            wv = w2[c]; fma2(a2, wv.x, hv.x); fma2(a2, wv.y, hv.y);
            wv = w3[c]; fma2(a3, wv.x, hv.x); fma2(a3, wv.y, hv.y);
        }
        float2 t;
        t = unpack2(a0); float gi = (t.x + t.y) + Pg0;
        t = unpack2(a1); float gf = (t.x + t.y) + Pg1;
        t = unpack2(a2); float gG = (t.x + t.y) + Pg2;
        t = unpack2(a3); float go = (t.x + t.y) + Pg3;

        float si = 1.f / (1.f + expf(-gi));
        float sf = 1.f / (1.f + expf(-gf));
        float so = 1.f / (1.f + expf(-go));
        creg = sf * creg + si * tanhf(gG);
        float h = so * tanhf(creg);

        // all-gather h(b,u) into every cluster CTA's next buffer
        #pragma unroll
        for (int r = 0; r < 8; r++)
            st_remote_f32(par ? remA[r] : remB[r], h);
        *hout = h;
        hout += hdelta;

        // split cluster barrier; next-step P prefetch hidden in the window
        asm volatile("barrier.cluster.arrive.aligned;" ::: "memory");
        if (step < 255) {
            Pg0 = pptr[0]; Pg1 = pptr[256]; Pg2 = pptr[512]; Pg3 = pptr[768];
            pptr += pdelta;
        }
        asm volatile("barrier.cluster.wait.aligned;" ::: "memory");
    }
}

// ---------------- kernel 3: output features F[r][t] ----------------
__global__ void __launch_bounds__(256) feats_kernel(
    const float* __restrict__ Wout, const float* __restrict__ bout) {
    int warp = threadIdx.x >> 5;
    int lane = threadIdx.x & 31;
    int r = blockIdx.x * 8 + warp;
    const float* hf = g_Hout + (size_t)r * 256;
    const float* hb = g_Hout + (size_t)NROWS * HID2 + (size_t)r * 256;
    float a[8], c[8];
    #pragma unroll
    for (int q = 0; q < 8; q++) { a[q] = hf[lane * 8 + q]; c[q] = hb[lane * 8 + q]; }
    #pragma unroll
    for (int t = 0; t < NTAG; t++) {
        const float* w = Wout + t * 512 + lane * 8;
        float s = 0.f;
        #pragma unroll
        for (int q = 0; q < 8; q++) s += a[q] * w[q] + c[q] * w[256 + q];
        #pragma unroll
        for (int off = 16; off; off >>= 1) s += __shfl_xor_sync(0xffffffffu, s, off);
        if (lane == 0) g_F[r * NTAG + t] = s + bout[t];
    }
}

// ---------------- kernel 4: Viterbi decode (one warp per batch) ----------------
__global__ void viterbi_kernel(const float* __restrict__ trans, float* __restrict__ out) {
    int b = blockIdx.x;
    int lane = threadIdx.x;
    __shared__ unsigned char bps[256][16];

    float tr[NTAG];
    if (lane < NTAG) {
        #pragma unroll
        for (int p = 0; p < NTAG; p++) tr[p] = trans[lane * NTAG + p];
    } else {
        #pragma unroll
        for (int p = 0; p < NTAG; p++) tr[p] = -10000.0f;
    }
    float fv = (lane == 8) ? 0.f : -10000.0f;   // START_IDX = 8
    const float* fb = g_F + b * (SEQ * NTAG);

    for (int s = 0; s < SEQ; s++) {
        float m = -3.4e38f; int arg = 0;
        #pragma unroll
        for (int p = 0; p < NTAG; p++) {
            float v = __shfl_sync(0xffffffffu, fv, p) + tr[p];
            if (v > m) { m = v; arg = p; }      // strict >: first-max wins (jnp.argmax)
        }
        float feat = 0.f;
        if (lane < NTAG) feat = fb[s * NTAG + lane];
        fv = m + feat;
        if (lane < NTAG) bps[s][lane] = (unsigned char)arg;
    }

    float term = fv;
    if (lane < NTAG) term += trans[9 * NTAG + lane];   // STOP_IDX row = 9
    float best = -3.4e38f; int bt = 0;
    #pragma unroll
    for (int t = 0; t < NTAG; t++) {
        float v = __shfl_sync(0xffffffffu, term, t);
        if (v > best) { best = v; bt = t; }
    }
    __syncwarp();
    if (lane == 0) {
        out[b] = best;                                   // path_score (B,1)
        int cur = bt;
        out[64 + b * SEQ + (SEQ - 1)] = (float)cur;      // path (B,S)
        for (int s = SEQ - 2; s >= 0; s--) {
            cur = bps[s + 1][cur];
            out[64 + b * SEQ + s] = (float)cur;
        }
    }
}

// ---------------- launch ----------------
extern "C" void kernel_launch(void* const* d_in, const int* in_sizes, int n_in,
                              void* d_out, int out_size) {
    const int*   sent  = (const int*)d_in[0];
    const float* emb   = (const float*)d_in[1];
    const float* wih_f = (const float*)d_in[2];
    const float* whh_f = (const float*)d_in[3];
    const float* bih_f = (const float*)d_in[4];
    const float* bhh_f = (const float*)d_in[5];
    const float* wih_b = (const float*)d_in[6];
    const float* whh_b = (const float*)d_in[7];
    const float* bih_b = (const float*)d_in[8];
    const float* bhh_b = (const float*)d_in[9];
    const float* Wout  = (const float*)d_in[10];
    const float* bout  = (const float*)d_in[11];

    // Dict order has transitions last; signature order has it at index 12.
    const float *trans, *h0, *c0;
    if (n_in > 14 && in_sizes[12] == 100) {
        trans = (const float*)d_in[12]; h0 = (const float*)d_in[13]; c0 = (const float*)d_in[14];
    } else {
        h0 = (const float*)d_in[12]; c0 = (const float*)d_in[13]; trans = (const float*)d_in[14];
    }
    float* out = (float*)d_out;

    transpose_wih<<<(EMB * NJ + 255) / 256, 256>>>(wih_f, wih_b);
    gemm_input<<<8192, 256>>>(sent, emb, bih_f, bhh_f, bih_b, bhh_b);

    const int smem_rec = (128 * 260 + 2 * 8 * 256) * (int)sizeof(float); // 149504 B
    cudaFuncSetAttribute(lstm_cluster, cudaFuncAttributeMaxDynamicSharedMemorySize, smem_rec);
    lstm_cluster<<<128, 256, smem_rec>>>(whh_f, whh_b, h0, c0);

    feats_kernel<<<NROWS / 8, 256>>>(Wout, bout);
    viterbi_kernel<<<BAT, 32>>>(trans, out);
}

// round 14
// speedup vs baseline: 2.1034x; 2.1034x over previous
#include <cuda_runtime.h>
#include <math.h>
#include <stdint.h>

// Problem constants
#define SEQ   256
#define BAT   64
#define EMB   300
#define HID2  256          // H2
#define NJ    2048         // 4*H2 * 2 directions
#define NTAG  10
#define NROWS 16384        // SEQ*BAT

typedef unsigned long long ull;

// ---------------- packed fp32x2 helpers (sm_103a FFMA2) ----------------
__device__ __forceinline__ void fma2(ull &d, ull a, ull b) {
    asm("fma.rn.f32x2 %0, %1, %2, %0;" : "+l"(d) : "l"(a), "l"(b));
}
__device__ __forceinline__ float2 unpack2(ull v) {
    float2 r; asm("mov.b64 {%0,%1}, %2;" : "=f"(r.x), "=f"(r.y) : "l"(v)); return r;
}

// ---------------- device scratch (static allocation only) ----------------
__device__ float    g_WT[EMB * NJ];                        // wih transposed, [e][j]
__device__ float    g_P[(size_t)NROWS * NJ];               // input projections + biases
// h exchange: [slot(2)][dir(2)][bg(8)][ug(8)][b(8)][u(32)]
__device__ float    g_hbuf[2 * 2 * 8 * 8 * 8 * 32];
__device__ float    g_Hout[2 * (size_t)NROWS * HID2];      // [dir][s*B+b][k]
__device__ float    g_F[NROWS * NTAG + 64];                // feats (B,S,T) flat, padded
// per-producer flags, one 128B line each: [dir][bg][ug]
__device__ unsigned g_flags[2 * 8 * 8 * 32];

// ---------------- kernel 0a: transpose wih into [e][j] ----------------
__global__ void transpose_wih(const float* __restrict__ wf, const float* __restrict__ wb) {
    int idx = blockIdx.x * 256 + threadIdx.x;
    if (idx >= EMB * NJ) return;
    int e = idx / NJ, j = idx % NJ;
    g_WT[idx] = (j < 1024) ? wf[j * EMB + e] : wb[(j - 1024) * EMB + e];
}

// ---------------- kernel 0b: zero flags + copy h0 into slot 0 ----------------
__global__ void init_state(const float* __restrict__ h0) {
    int idx = blockIdx.x * 256 + threadIdx.x;
    if (idx < 2 * 8 * 8 * 32) g_flags[idx] = 0u;
    if (idx < 2 * BAT * HID2) {
        // h0 is [dir][b][k]
        int dir = idx >> 14;
        int bglob = (idx >> 8) & 63;
        int k = idx & 255;
        int bg = bglob >> 3, bl = bglob & 7;
        int ug = k >> 5, u = k & 31;
        g_hbuf[(((0 * 2 + dir) * 8 + bg) * 8 + ug) * 256 + bl * 32 + u] = h0[idx];
    }
}

// ---------------- kernel 1: fused gather + input GEMM (fp32, 64x64 tile) ----
// P[r][j] = sum_e emb[sent[r]][e] * WT[e][j] + bih[j] + bhh[j]
__global__ void __launch_bounds__(256) gemm_input(
    const int* __restrict__ sent, const float* __restrict__ emb,
    const float* __restrict__ bih_f, const float* __restrict__ bhh_f,
    const float* __restrict__ bih_b, const float* __restrict__ bhh_b) {

    __shared__ float As[20][68];   // [k][i], padded stride 68
    __shared__ float Bs[20][64];   // [k][j]
    __shared__ int   toks[64];

    int bx = blockIdx.x & 31;      // N tile (32)
    int by = blockIdx.x >> 5;      // M tile (256)
    int tid = threadIdx.x;
    int row0 = by * 64, col0 = bx * 64;

    if (tid < 64) toks[tid] = sent[row0 + tid];
    __syncthreads();

    int ty = tid >> 4, tx = tid & 15;         // 16x16 thread grid
    int li = tid >> 2;                        // A-load row
    int le = (tid & 3) * 5;                   // A-load e base

    float4 acc[4];
    #pragma unroll
    for (int i = 0; i < 4; i++) acc[i] = make_float4(0.f, 0.f, 0.f, 0.f);

    long tokoff = (long)toks[li] * EMB;

    for (int kc = 0; kc < 15; kc++) {
        int e0 = kc * 20;
        const float* ebase = emb + tokoff + e0 + le;
        #pragma unroll
        for (int q = 0; q < 5; q++) As[le + q][li] = ebase[q];
        #pragma unroll
        for (int u = 0; u < 5; u++) {
            int idx = tid + u * 256;
            int kk = idx >> 6, j = idx & 63;
            Bs[kk][j] = g_WT[(size_t)(e0 + kk) * NJ + col0 + j];
        }
        __syncthreads();
        #pragma unroll
        for (int kk = 0; kk < 20; kk++) {
            float4 b4 = *(const float4*)&Bs[kk][tx * 4];
            float4 a4 = *(const float4*)&As[kk][ty * 4];
            acc[0].x += a4.x * b4.x; acc[0].y += a4.x * b4.y; acc[0].z += a4.x * b4.z; acc[0].w += a4.x * b4.w;
            acc[1].x += a4.y * b4.x; acc[1].y += a4.y * b4.y; acc[1].z += a4.y * b4.z; acc[1].w += a4.y * b4.w;
            acc[2].x += a4.z * b4.x; acc[2].y += a4.z * b4.y; acc[2].z += a4.z * b4.z; acc[2].w += a4.z * b4.w;
            acc[3].x += a4.w * b4.x; acc[3].y += a4.w * b4.y; acc[3].z += a4.w * b4.z; acc[3].w += a4.w * b4.w;
        }
        __syncthreads();
    }

    int jg = col0 + tx * 4;
    float bias[4];
    #pragma unroll
    for (int jj = 0; jj < 4; jj++) {
        int j = jg + jj;
        bias[jj] = (j < 1024) ? (bih_f[j] + bhh_f[j]) : (bih_b[j - 1024] + bhh_b[j - 1024]);
    }
    #pragma unroll
    for (int ii = 0; ii < 4; ii++) {
        float4 v = acc[ii];
        v.x += bias[0]; v.y += bias[1]; v.z += bias[2]; v.w += bias[3];
        *(float4*)&g_P[(size_t)(row0 + ty * 4 + ii) * NJ + jg] = v;
    }
}

// ---------------- kernel 2: persistent bidirectional LSTM recurrence ----------------
// 128 CTAs = dir(2) x batch-group bg(8) x unit-group ug(8).
// CTA holds 128 Whh rows (its 32 units x 4 gates) in SMEM for all steps and
// needs h only for its 8 batches (8KB/step from L2, guarded by 8 flags).
// Compute: warp = k-slice (32 k), lane = unit; acc[gate][batch] packed over
// k-pairs (FMA2, no pack instr). k-slice partials combined via padded SMEM
// staging. Cell state lives in a register (thread (b,u) fixed).
__global__ void __launch_bounds__(256, 1) lstm_recurrent(
    const float* __restrict__ whh_f, const float* __restrict__ whh_b,
    const float* __restrict__ c0) {

    extern __shared__ float sm[];
    float* w_s = sm;                     // 128 rows * stride 260 = 33280
    float* h_s = sm + 33280;             // 8 batches * stride 260 = 2080
    float* gs  = h_s + 2080;             // 32 (g*8+b) rows * stride 296 = 9472
    // total 44832 floats = 179328 B

    const int tid = threadIdx.x;
    const int dir = blockIdx.x >> 6;
    const int bg  = (blockIdx.x >> 3) & 7;
    const int ug  = blockIdx.x & 7;
    const float* whh = dir ? whh_b : whh_f;

    // Load Whh slice: local row rho = g*32+u -> global row g*256 + ug*32 + u
    for (int idx = tid; idx < 128 * 64; idx += 256) {
        int rho = idx >> 6, kq = idx & 63;
        int grow = (rho >> 5) * 256 + ug * 32 + (rho & 31);
        float4 v = *(const float4*)&whh[(size_t)grow * 256 + kq * 4];
        *(float4*)&w_s[rho * 260 + kq * 4] = v;
    }
    __syncthreads();

    const int lane = tid & 31, wrp = tid >> 5;
    // compute mapping: warp = k-slice ks, lane = unit ul
    const int ks = wrp, ul = lane;
    // finalize / producer mapping: warp = batch b2, lane = unit u2
    const int b2 = wrp, u2 = lane;

    float creg = c0[(size_t)(dir * 64 + bg * 8 + b2) * 256 + ug * 32 + u2];

    // W row pointers for the 4 gates (ulonglong2 units; row stride 260 fl = 65 units)
    const ulonglong2* wp0 = (const ulonglong2*)(w_s + (0 * 32 + ul) * 260 + ks * 32);
    const ulonglong2* wp1 = (const ulonglong2*)(w_s + (1 * 32 + ul) * 260 + ks * 32);
    const ulonglong2* wp2 = (const ulonglong2*)(w_s + (2 * 32 + ul) * 260 + ks * 32);
    const ulonglong2* wp3 = (const ulonglong2*)(w_s + (3 * 32 + ul) * 260 + ks * 32);

    // chunk copy mapping: warp w fetches chunk ug'=w; lane: cb = batch, cq = quarter
    const int cb = lane >> 2, cq = lane & 3;
    unsigned* myflag  = &g_flags[((dir * 8 + bg) * 8 + wrp) * 32];
    unsigned* ownflag = &g_flags[((dir * 8 + bg) * 8 + ug) * 32];

    // P walk: thread (b2,u2), gates at +g*256
    const float* pptr = g_P + (size_t)((dir ? 255 : 0) * 64 + bg * 8 + b2) * NJ
                      + dir * 1024 + ug * 32 + u2;
    const long pdelta = dir ? -(long)(64 * NJ) : (long)(64 * NJ);
    // Hout walk
    float* hout = g_Hout + (size_t)dir * ((size_t)NROWS * HID2)
                + (size_t)(((dir ? 255 : 0) * 64) + bg * 8 + b2) * 256 + ug * 32 + u2;
    const long hdelta = dir ? -(long)(64 * 256) : (long)(64 * 256);

    for (int step = 0; step < 256; step++) {
        int slot = step & 1;

        // prefetch P gate biases (independent of flags/h)
        float Pg0 = pptr[0], Pg1 = pptr[256], Pg2 = pptr[512], Pg3 = pptr[768];
        pptr += pdelta;

        // 1. wait for chunk ug'=wrp of h(step), copy 1KB into h_s[b][k]
        {
            unsigned v;
            do {
                asm volatile("ld.acquire.gpu.b32 %0, [%1];" : "=r"(v) : "l"(myflag) : "memory");
            } while ((int)v < step);
            const float4* src = (const float4*)(g_hbuf
                + (size_t)(((slot * 2 + dir) * 8 + bg) * 8 + wrp) * 256);
            float4 v0 = __ldcg(src + cb * 8 + cq * 2);
            float4 v1 = __ldcg(src + cb * 8 + cq * 2 + 1);
            *(float4*)&h_s[cb * 260 + wrp * 32 + cq * 8]     = v0;
            *(float4*)&h_s[cb * 260 + wrp * 32 + cq * 8 + 4] = v1;
        }
        __syncthreads();

        // 2. partial dot products: acc[g][b] = k-pair-packed sums over this k-slice
        ull acc[4][8];
        #pragma unroll
        for (int g = 0; g < 4; g++)
            #pragma unroll
            for (int b = 0; b < 8; b++) acc[g][b] = 0ULL;

        const ulonglong2* hp = (const ulonglong2*)(h_s + ks * 32);
        #pragma unroll
        for (int i = 0; i < 8; i++) {
            ulonglong2 w0v = wp0[i], w1v = wp1[i], w2v = wp2[i], w3v = wp3[i];
            #pragma unroll
            for (int b = 0; b < 8; b++) {
                ulonglong2 hv = hp[b * 65 + i];    // warp-broadcast LDS.128
                fma2(acc[0][b], w0v.x, hv.x); fma2(acc[0][b], w0v.y, hv.y);
                fma2(acc[1][b], w1v.x, hv.x); fma2(acc[1][b], w1v.y, hv.y);
                fma2(acc[2][b], w2v.x, hv.x); fma2(acc[2][b], w2v.y, hv.y);
                fma2(acc[3][b], w3v.x, hv.x); fma2(acc[3][b], w3v.y, hv.y);
            }
        }
        // 3. stage partials: gs[(g*8+b)*296 + ul*9 + ks]
        #pragma unroll
        for (int g = 0; g < 4; g++)
            #pragma unroll
            for (int b = 0; b < 8; b++) {
                float2 t = unpack2(acc[g][b]);
                gs[(g * 8 + b) * 296 + ul * 9 + ks] = t.x + t.y;
            }
        __syncthreads();

        // 4. finalize gates for (b2, u2): sum 8 k-slices + P
        float gv[4];
        #pragma unroll
        for (int g = 0; g < 4; g++) {
            const float* row = gs + (g * 8 + b2) * 296 + u2 * 9;
            float s01 = row[0] + row[1];
            float s23 = row[2] + row[3];
            float s45 = row[4] + row[5];
            float s67 = row[6] + row[7];
            gv[g] = (s01 + s23) + (s45 + s67);
        }
        float gi = gv[0] + Pg0;
        float gf = gv[1] + Pg1;
        float gG = gv[2] + Pg2;
        float go = gv[3] + Pg3;

        float si = 1.f / (1.f + expf(-gi));
        float sf = 1.f / (1.f + expf(-gf));
        float so = 1.f / (1.f + expf(-go));
        creg = sf * creg + si * tanhf(gG);
        float h = so * tanhf(creg);

        // 5. publish h(step+1): own chunk, contiguous 1KB, coalesced per warp
        __stcg(&g_hbuf[(size_t)((((slot ^ 1) * 2 + dir) * 8 + bg) * 8 + ug) * 256
                       + b2 * 32 + u2], h);
        *hout = h;
        hout += hdelta;

        // 6. release flag = step+1
        __syncthreads();
        __threadfence();
        if (tid == 0) {
            unsigned nv = (unsigned)(step + 1);
            asm volatile("st.release.gpu.b32 [%0], %1;" :: "l"(ownflag), "r"(nv) : "memory");
        }
    }
}

// ---------------- kernel 3: output features F[r][t] ----------------
__global__ void __launch_bounds__(256) feats_kernel(
    const float* __restrict__ Wout, const float* __restrict__ bout) {
    int warp = threadIdx.x >> 5;
    int lane = threadIdx.x & 31;
    int r = blockIdx.x * 8 + warp;
    const float* hf = g_Hout + (size_t)r * 256;
    const float* hb = g_Hout + (size_t)NROWS * HID2 + (size_t)r * 256;
    float a[8], c[8];
    #pragma unroll
    for (int q = 0; q < 8; q++) { a[q] = hf[lane * 8 + q]; c[q] = hb[lane * 8 + q]; }
    #pragma unroll
    for (int t = 0; t < NTAG; t++) {
        const float* w = Wout + t * 512 + lane * 8;
        float s = 0.f;
        #pragma unroll
        for (int q = 0; q < 8; q++) s += a[q] * w[q] + c[q] * w[256 + q];
        #pragma unroll
        for (int off = 16; off; off >>= 1) s += __shfl_xor_sync(0xffffffffu, s, off);
        if (lane == 0) g_F[r * NTAG + t] = s + bout[t];
    }
}

// ---------------- kernel 4: Viterbi decode (one warp per batch) ----------------
__global__ void viterbi_kernel(const float* __restrict__ trans, float* __restrict__ out) {
    int b = blockIdx.x;
    int lane = threadIdx.x;
    __shared__ unsigned char bps[256][16];

    float tr[NTAG];
    if (lane < NTAG) {
        #pragma unroll
        for (int p = 0; p < NTAG; p++) tr[p] = trans[lane * NTAG + p];
    } else {
        #pragma unroll
        for (int p = 0; p < NTAG; p++) tr[p] = -10000.0f;
    }
    float fv = (lane == 8) ? 0.f : -10000.0f;   // START_IDX = 8
    const float* fb = g_F + b * (SEQ * NTAG);

    for (int s = 0; s < SEQ; s++) {
        float m = -3.4e38f; int arg = 0;
        #pragma unroll
        for (int p = 0; p < NTAG; p++) {
            float v = __shfl_sync(0xffffffffu, fv, p) + tr[p];
            if (v > m) { m = v; arg = p; }      // strict >: first-max wins (jnp.argmax)
        }
        float feat = 0.f;
        if (lane < NTAG) feat = fb[s * NTAG + lane];
        fv = m + feat;
        if (lane < NTAG) bps[s][lane] = (unsigned char)arg;
    }

    float term = fv;
    if (lane < NTAG) term += trans[9 * NTAG + lane];   // STOP_IDX row = 9
    float best = -3.4e38f; int bt = 0;
    #pragma unroll
    for (int t = 0; t < NTAG; t++) {
        float v = __shfl_sync(0xffffffffu, term, t);
        if (v > best) { best = v; bt = t; }
    }
    __syncwarp();
    if (lane == 0) {
        out[b] = best;                                   // path_score (B,1)
        int cur = bt;
        out[64 + b * SEQ + (SEQ - 1)] = (float)cur;      // path (B,S)
        for (int s = SEQ - 2; s >= 0; s--) {
            cur = bps[s + 1][cur];
            out[64 + b * SEQ + s] = (float)cur;
        }
    }
}

// ---------------- launch ----------------
extern "C" void kernel_launch(void* const* d_in, const int* in_sizes, int n_in,
                              void* d_out, int out_size) {
    const int*   sent  = (const int*)d_in[0];
    const float* emb   = (const float*)d_in[1];
    const float* wih_f = (const float*)d_in[2];
    const float* whh_f = (const float*)d_in[3];
    const float* bih_f = (const float*)d_in[4];
    const float* bhh_f = (const float*)d_in[5];
    const float* wih_b = (const float*)d_in[6];
    const float* whh_b = (const float*)d_in[7];
    const float* bih_b = (const float*)d_in[8];
    const float* bhh_b = (const float*)d_in[9];
    const float* Wout  = (const float*)d_in[10];
    const float* bout  = (const float*)d_in[11];

    // Dict order has transitions last; signature order has it at index 12.
    const float *trans, *h0, *c0;
    if (n_in > 14 && in_sizes[12] == 100) {
        trans = (const float*)d_in[12]; h0 = (const float*)d_in[13]; c0 = (const float*)d_in[14];
    } else {
        h0 = (const float*)d_in[12]; c0 = (const float*)d_in[13]; trans = (const float*)d_in[14];
    }
    float* out = (float*)d_out;

    transpose_wih<<<(EMB * NJ + 255) / 256, 256>>>(wih_f, wih_b);
    init_state<<<128, 256>>>(h0);
    gemm_input<<<8192, 256>>>(sent, emb, bih_f, bhh_f, bih_b, bhh_b);

    const int smem_rec = 44832 * (int)sizeof(float); // 179328 B
    cudaFuncSetAttribute(lstm_recurrent, cudaFuncAttributeMaxDynamicSharedMemorySize, smem_rec);
    lstm_recurrent<<<128, 256, smem_rec>>>(whh_f, whh_b, c0);

    feats_kernel<<<NROWS / 8, 256>>>(Wout, bout);
    viterbi_kernel<<<BAT, 32>>>(trans, out);
}